// round 1
// baseline (speedup 1.0000x reference)
#include <cuda_runtime.h>
#include <cuda_bf16.h>

#define NPW 16
#define M   64
#define NT  256
#define OBJ 10

// plin eval matching reference semantics exactly:
//   y = 16*x; idx = trunc(y) (== clip(int(y),0,16) for y in [-1+eps, 16+eps]);
//   frac = y - floor(y); val = csum[idx] + frac * w[min(idx+1,16)]
// Table t[idx] = (csum[idx], w[min(idx+1,16)]).
__device__ __forceinline__ float plin_eval(const float2* __restrict__ t, float x) {
    float y  = 16.0f * x;
    int  idx = (int)y;             // trunc-to-zero: negative eps -> 0, matches clip
    float fr = y - floorf(y);      // matches reference (floor, not trunc)
    float2 v = t[idx];
    return fmaf(fr, v.y, v.x);
}

// Replicated-table variant for the hot loop: t points at rep2 + lane,
// entries strided by 32 -> bank-conflict-free LDS.64.
__device__ __forceinline__ float plin_eval_rep(const float2* __restrict__ t, float y) {
    int  idx = (int)y;
    float fr = y - floorf(y);
    float2 v = t[idx * 32];
    return fmaf(fr, v.y, v.x);
}

__global__ __launch_bounds__(NT, 1)
void counter_kernel(const float* __restrict__ boxes,   // (n,4,64)
                    const float* __restrict__ attn,    // (n,64)
                    const float* __restrict__ fw,      // (16,17)
                    float* __restrict__ out)           // (n,11)
{
    __shared__ float2 tab[8][NPW + 1];        // (csum, w_next) per fn
    __shared__ float2 rep2[(NPW + 1) * 32];   // f2 table replicated per lane
    __shared__ float  ds[M * M];
    __shared__ float  Am[M * M];
    __shared__ float  att_s[M], area_s[M];
    __shared__ float  bx1[M], by1[M], bx2[M], by2[M];
    __shared__ float  part[4 * M];            // row_sims partials
    __shared__ float  rowinv[M];
    __shared__ float  redA[NT], redB[NT];

    const int tid = threadIdx.x;
    const int bi  = blockIdx.x;

    // ---- Phase 0: build plin tables (fns 0..7) ----
    if (tid < 8) {
        const int fn = tid;
        float w[NPW + 1];
        float s = 0.0f;
        #pragma unroll
        for (int i = 0; i <= NPW; i++) { w[i] = fabsf(fw[fn * (NPW + 1) + i]); s += w[i]; }
        #pragma unroll
        for (int i = 0; i <= NPW; i++) w[i] = w[i] / s;
        float c = 0.0f;
        #pragma unroll
        for (int i = 0; i <= NPW; i++) {
            c += w[i];
            float wn = w[(i + 1 <= NPW) ? (i + 1) : NPW];
            tab[fn][i] = make_float2(c, wn);
        }
    }
    __syncthreads();

    // ---- Phase 1: replicate f2 table, load inputs, areas ----
    for (int e = tid; e < (NPW + 1) * 32; e += NT)
        rep2[e] = tab[2][e >> 5];
    if (tid < M) {
        const int j = tid;
        att_s[j] = attn[bi * M + j];
        float x1 = boxes[(bi * 4 + 0) * M + j];
        float y1 = boxes[(bi * 4 + 1) * M + j];
        float x2 = boxes[(bi * 4 + 2) * M + j];
        float y2 = boxes[(bi * 4 + 3) * M + j];
        bx1[j] = x1; by1[j] = y1; bx2[j] = x2; by2[j] = y2;
        area_s[j] = fmaxf(x2 - x1, 0.0f) * fmaxf(y2 - y1, 0.0f);
    }
    __syncthreads();

    // ---- Phase 2: dist/IoU, A = f0*f1, ds = f3*f4, dist_conf partial ----
    // Thread handles column c (lane-consecutive) x 16 rows r.
    const int c  = tid & 63;
    const int rb = tid >> 6;
    float attc = att_s[c];
    float x1c = bx1[c], y1c = by1[c], x2c = bx2[c], y2c = by2[c], arc = area_s[c];

    float attconf = 0.0f;
    if (tid < M) {
        float f5v = plin_eval(tab[5], att_s[tid]);
        attconf = fabsf(f5v - 0.5f);
    }

    float dconf_local = 0.0f;
    #pragma unroll 4
    for (int it = 0; it < 16; it++) {
        const int r = rb + 4 * it;
        float rel  = att_s[r] * attc;
        float ix = fminf(bx2[r], x2c) - fmaxf(bx1[r], x1c);
        float iy = fminf(by2[r], y2c) - fmaxf(by1[r], y1c);
        ix = fmaxf(ix, 0.0f); iy = fmaxf(iy, 0.0f);
        float inter = ix * iy;
        float den   = area_s[r] + arc - inter + 1e-12f;
        float iouv  = inter / den;
        float dist  = 1.0f - iouv;

        float f0v = plin_eval(tab[0], rel);
        float f1v = plin_eval(tab[1], dist);
        float f3v = plin_eval(tab[3], rel);
        float f4v = plin_eval(tab[4], dist);
        float f6v = plin_eval(tab[6], dist);

        Am[r * M + c] = f0v * f1v;
        ds[r * M + c] = f3v * f4v;
        dconf_local += fabsf(f6v - 0.5f);
    }
    __syncthreads();

    // ---- Phase 3: sim products (m^3 hot loop) ----
    // Thread owns fixed j = tid&63 (lane-consecutive) and 16 k's (warp-constant).
    const int j  = tid & 63;
    const int kb = tid >> 6;
    const float2* trep = rep2 + (tid & 31);

    float prod[16];
    #pragma unroll
    for (int q = 0; q < 16; q++) prod[q] = 1.0f;

    for (int l = 0; l < M; l++) {
        const float dsj = ds[l * M + j];
        #pragma unroll
        for (int q = 0; q < 16; q++) {
            const int k = kb + 4 * q;
            float dsk  = ds[l * M + k];          // warp-broadcast
            float diff = fabsf(dsj - dsk);
            float y    = fmaf(-16.0f, diff, 16.0f);
            prod[q] *= plin_eval_rep(trep, y);
        }
    }

    // apply att_diff factor, accumulate row_sims partial (fixed j per thread)
    const float attj = att_s[j];
    float rsum_local = 0.0f;
    #pragma unroll
    for (int q = 0; q < 16; q++) {
        const int k = kb + 4 * q;
        float ad = fabsf(attj - att_s[k]);
        float y  = fmaf(-16.0f, ad, 16.0f);
        float simv = prod[q] * plin_eval_rep(trep, y);
        rsum_local += simv;
    }
    part[kb * M + j] = rsum_local;
    __syncthreads();

    if (tid < M) {
        float rs = part[tid] + part[M + tid] + part[2 * M + tid] + part[3 * M + tid];
        rowinv[tid] = 1.0f / rs;
    }
    __syncthreads();

    // ---- Phase 4: score sum  S = sum_{j,k} A[j,k]*inv[j]*inv[k] + sum_j f0(att^2)*inv[j]
    float sA = 0.0f;
    #pragma unroll
    for (int q = 0; q < 16; q++) {
        const int k = kb + 4 * q;
        sA += Am[k * M + j] * rowinv[k];   // A symmetric: read lane-consecutive
    }
    sA *= rowinv[j];

    float corr = 0.0f;
    if (tid < M) {
        float a = att_s[tid];
        corr = plin_eval(tab[0], a * a) * rowinv[tid];
    }

    redA[tid] = sA + corr;
    redB[tid] = dconf_local * (1.0f / 4096.0f) + attconf * (1.0f / 64.0f);
    __syncthreads();

    #pragma unroll
    for (int s = NT / 2; s > 0; s >>= 1) {
        if (tid < s) { redA[tid] += redA[tid + s]; redB[tid] += redB[tid + s]; }
        __syncthreads();
    }

    // ---- Phase 5: score -> one-hot * conf ----
    if (tid == 0) {
        float S     = redA[0];
        float score = sqrtf(S + 1e-20f);
        float conf  = plin_eval(tab[7], redB[0]);

        float sc  = fminf(fmaxf(score, 0.0f), (float)OBJ);
        int   i0  = (int)sc;
        float fr  = sc - floorf(sc);
        int   i1  = (i0 + 1 <= OBJ) ? (i0 + 1) : OBJ;

        #pragma unroll
        for (int o = 0; o <= OBJ; o++) {
            float v = 0.0f;
            if (o == i0) v += (1.0f - fr);
            if (o == i1) v += fr;
            out[bi * (OBJ + 1) + o] = conf * v;
        }
    }
}

extern "C" void kernel_launch(void* const* d_in, const int* in_sizes, int n_in,
                              void* d_out, int out_size) {
    const float* boxes = (const float*)d_in[0];   // (n,4,64)
    const float* attn  = (const float*)d_in[1];   // (n,64)
    const float* fwts  = (const float*)d_in[2];   // (16,17)
    float* out = (float*)d_out;                   // (n,11)

    const int n = in_sizes[1] / M;                // 128
    counter_kernel<<<n, NT>>>(boxes, attn, fwts, out);
}

// round 2
// speedup vs baseline: 1.3503x; 1.3503x over previous
#include <cuda_runtime.h>
#include <cuda_bf16.h>

#define NPW 16
#define M   64
#define NT  512
#define OBJ 10
#define NPAIRS 2016   // 64*63/2 off-diagonal pairs (j<k)
#define PPT 4         // pairs per thread: 512*4 = 2048 >= 2016

// plin eval matching reference semantics exactly:
//   y = 16*x; idx = trunc(y) (== clip(int32(y),0,16) for y in [-1+eps, 16+eps]);
//   frac = y - floor(y); val = csum[idx] + frac * w[min(idx+1,16)]
__device__ __forceinline__ float plin_eval(const float2* __restrict__ t, float x) {
    float y  = 16.0f * x;
    int  idx = (int)y;
    float fr = y - floorf(y);
    float2 v = t[idx];
    return fmaf(fr, v.y, v.x);
}

// Replicated-table variant: t = rep2 + lane; entries strided by 32 lanes
// -> LDS.64 half-warp phases hit all 32 banks once -> conflict-free.
__device__ __forceinline__ float plin_eval_rep(const float2* __restrict__ t, float y) {
    int  idx = (int)y;
    float fr = y - floorf(y);
    float2 v = t[idx * 32];
    return fmaf(fr, v.y, v.x);
}

__global__ __launch_bounds__(NT, 1)
void counter_kernel(const float* __restrict__ boxes,   // (n,4,64)
                    const float* __restrict__ attn,    // (n,64)
                    const float* __restrict__ fw,      // (16,17)
                    float* __restrict__ out)           // (n,11)
{
    __shared__ float2 tab[8][NPW + 1];          // (csum, w_next) per fn
    __shared__ float2 rep2[(NPW + 1) * 32];     // f2 table replicated per lane
    __shared__ float  ds[M * M];                // dedup scores
    __shared__ float  sim[M * M];               // full sim matrix
    __shared__ unsigned short pairs[NT * PPT];  // packed (j | k<<8)
    __shared__ float  att_s[M], area_s[M];
    __shared__ float  bx1[M], by1[M], bx2[M], by2[M];
    __shared__ float  part[8 * M];
    __shared__ float  rowinv[M];
    __shared__ float  wredA[NT / 32], wredB[NT / 32];

    const int tid = threadIdx.x;
    const int bi  = blockIdx.x;

    // ---- Phase 0: build plin tables (fns 0..7) ----
    if (tid < 8) {
        const int fn = tid;
        float w[NPW + 1];
        float s = 0.0f;
        #pragma unroll
        for (int i = 0; i <= NPW; i++) { w[i] = fabsf(fw[fn * (NPW + 1) + i]); s += w[i]; }
        #pragma unroll
        for (int i = 0; i <= NPW; i++) w[i] = w[i] / s;
        float c = 0.0f;
        #pragma unroll
        for (int i = 0; i <= NPW; i++) {
            c += w[i];
            float wn = w[(i + 1 <= NPW) ? (i + 1) : NPW];
            tab[fn][i] = make_float2(c, wn);
        }
    }
    __syncthreads();

    // ---- Phase 1: replicate f2 table, pair table, inputs ----
    for (int e = tid; e < (NPW + 1) * 32; e += NT)
        rep2[e] = tab[2][e >> 5];

    // pairs ordered diagonal-major: d=1..63, j=0..63-d, k=j+d.
    // Consecutive p -> consecutive j (and k) -> conflict-free lane access.
    for (int p = tid; p < NT * PPT; p += NT) {
        int j = 0, k = 0;
        if (p < NPAIRS) {
            int cum = 0;
            for (int d = 1; d < 64; d++) {
                int len = 64 - d;
                if (p < cum + len) { j = p - cum; k = j + d; break; }
                cum += len;
            }
        }
        pairs[p] = (unsigned short)(j | (k << 8));
    }

    if (tid < M) {
        const int j = tid;
        att_s[j] = attn[bi * M + j];
        float x1 = boxes[(bi * 4 + 0) * M + j];
        float y1 = boxes[(bi * 4 + 1) * M + j];
        float x2 = boxes[(bi * 4 + 2) * M + j];
        float y2 = boxes[(bi * 4 + 3) * M + j];
        bx1[j] = x1; by1[j] = y1; bx2[j] = x2; by2[j] = y2;
        area_s[j] = fmaxf(x2 - x1, 0.0f) * fmaxf(y2 - y1, 0.0f);
    }
    __syncthreads();

    // ---- Phase 2: ds = f3(rel)*f4(dist), dconf, attconf, sim diagonal ----
    const int c  = tid & 63;       // column (lane-consecutive)
    const int rb = tid >> 6;       // 0..7 row group
    const float attc = att_s[c];
    const float x1c = bx1[c], y1c = by1[c], x2c = bx2[c], y2c = by2[c], arc = area_s[c];

    float attconf = 0.0f;
    if (tid < M)
        attconf = fabsf(plin_eval(tab[5], att_s[tid]) - 0.5f);

    float dconf_local = 0.0f;
    #pragma unroll
    for (int it = 0; it < 8; it++) {
        const int r = rb + 8 * it;
        float rel  = att_s[r] * attc;
        float ix = fminf(bx2[r], x2c) - fmaxf(bx1[r], x1c);
        float iy = fminf(by2[r], y2c) - fmaxf(by1[r], y1c);
        ix = fmaxf(ix, 0.0f); iy = fmaxf(iy, 0.0f);
        float inter = ix * iy;
        float dist  = 1.0f - inter / (area_s[r] + arc - inter + 1e-12f);

        ds[r * M + c] = plin_eval(tab[3], rel) * plin_eval(tab[4], dist);
        dconf_local += fabsf(plin_eval(tab[6], dist) - 0.5f);
    }

    // diagonal of sim: f2(1)^65 = csum2[16]^65 (same mult chain as reference)
    if (tid < M) {
        float cv = tab[2][NPW].x;
        float pr = 1.0f;
        #pragma unroll
        for (int i = 0; i < M; i++) pr *= cv;
        pr *= cv;
        sim[tid * M + tid] = pr;
    }
    __syncthreads();

    // ---- Phase 3: hot m^3 loop over off-diagonal pairs (symmetry-halved) ----
    int jj[PPT], kk[PPT];
    #pragma unroll
    for (int q = 0; q < PPT; q++) {
        unsigned short pk = pairs[tid + NT * q];
        jj[q] = pk & 255;
        kk[q] = pk >> 8;
    }

    float prod[PPT];
    #pragma unroll
    for (int q = 0; q < PPT; q++) prod[q] = 1.0f;

    const float2* trep = rep2 + (tid & 31);

    for (int l = 0; l < M; l++) {
        const float* __restrict__ row = ds + l * M;
        #pragma unroll
        for (int q = 0; q < PPT; q++) {
            float a = row[jj[q]];
            float b = row[kk[q]];
            float diff = fabsf(a - b);
            float y = fmaf(-16.0f, diff, 16.0f);
            prod[q] *= plin_eval_rep(trep, y);
        }
    }

    #pragma unroll
    for (int q = 0; q < PPT; q++) {
        const int p = tid + NT * q;
        if (p < NPAIRS) {
            const int j = jj[q], k = kk[q];
            float ad = fabsf(att_s[j] - att_s[k]);
            float y  = fmaf(-16.0f, ad, 16.0f);
            float sv = prod[q] * plin_eval_rep(trep, y);
            sim[j * M + k] = sv;
            sim[k * M + j] = sv;
        }
    }
    __syncthreads();

    // ---- Phase 4: row sums (read column-wise: conflict-free) -> rowinv ----
    {
        float s = 0.0f;
        #pragma unroll
        for (int i = 0; i < 8; i++) {
            const int k = rb * 8 + i;
            s += sim[k * M + c];
        }
        part[rb * M + c] = s;
    }
    __syncthreads();
    if (tid < M) {
        float rs = 0.0f;
        #pragma unroll
        for (int g = 0; g < 8; g++) rs += part[g * M + tid];
        rowinv[tid] = 1.0f / rs;
    }
    __syncthreads();

    // ---- Phase 5: recompute A = f0*f1, accumulate score ----
    float accA = 0.0f;
    #pragma unroll
    for (int it = 0; it < 8; it++) {
        const int r = rb + 8 * it;
        float rel  = att_s[r] * attc;
        float ix = fminf(bx2[r], x2c) - fmaxf(bx1[r], x1c);
        float iy = fminf(by2[r], y2c) - fmaxf(by1[r], y1c);
        ix = fmaxf(ix, 0.0f); iy = fmaxf(iy, 0.0f);
        float inter = ix * iy;
        float dist  = 1.0f - inter / (area_s[r] + arc - inter + 1e-12f);
        float Av = plin_eval(tab[0], rel) * plin_eval(tab[1], dist);
        accA += Av * rowinv[r];
    }
    accA *= rowinv[c];

    float corr = 0.0f;
    if (tid < M) {
        float a = att_s[tid];
        corr = plin_eval(tab[0], a * a) * rowinv[tid];
    }

    float ra  = accA + corr;
    float rbv = dconf_local * (1.0f / 4096.0f) + attconf * (1.0f / 64.0f);

    #pragma unroll
    for (int off = 16; off > 0; off >>= 1) {
        ra  += __shfl_down_sync(0xffffffffu, ra,  off);
        rbv += __shfl_down_sync(0xffffffffu, rbv, off);
    }
    if ((tid & 31) == 0) {
        wredA[tid >> 5] = ra;
        wredB[tid >> 5] = rbv;
    }
    __syncthreads();

    // ---- Phase 6: score -> one-hot * conf ----
    if (tid == 0) {
        float S = 0.0f, B = 0.0f;
        #pragma unroll
        for (int i = 0; i < NT / 32; i++) { S += wredA[i]; B += wredB[i]; }

        float score = sqrtf(S + 1e-20f);
        float conf  = plin_eval(tab[7], B);

        float sc  = fminf(fmaxf(score, 0.0f), (float)OBJ);
        int   i0  = (int)sc;
        float fr  = sc - floorf(sc);
        int   i1  = (i0 + 1 <= OBJ) ? (i0 + 1) : OBJ;

        #pragma unroll
        for (int o = 0; o <= OBJ; o++) {
            float v = 0.0f;
            if (o == i0) v += (1.0f - fr);
            if (o == i1) v += fr;
            out[bi * (OBJ + 1) + o] = conf * v;
        }
    }
}

extern "C" void kernel_launch(void* const* d_in, const int* in_sizes, int n_in,
                              void* d_out, int out_size) {
    const float* boxes = (const float*)d_in[0];   // (n,4,64)
    const float* attn  = (const float*)d_in[1];   // (n,64)
    const float* fwts  = (const float*)d_in[2];   // (16,17)
    float* out = (float*)d_out;                   // (n,11)

    const int n = in_sizes[1] / M;                // 128
    counter_kernel<<<n, NT>>>(boxes, attn, fwts, out);
}

// round 3
// speedup vs baseline: 1.3672x; 1.0125x over previous
#include <cuda_runtime.h>
#include <cuda_bf16.h>

#define NPW 16
#define M   64
#define NT  768
#define NW  (NT / 32)
#define OBJ 10
#define NPAIRS 2016   // 64*63/2 off-diagonal pairs (j<k)
#define PPT 3         // 768*3 = 2304 >= 2016

// plin eval matching reference semantics exactly:
//   y = 16*x; idx = trunc(y); frac = y - floor(y); val = csum[idx] + frac*w[min(idx+1,16)]
__device__ __forceinline__ float plin_eval(const float2* __restrict__ t, float x) {
    float y  = 16.0f * x;
    int  idx = (int)y;
    float fr = y - floorf(y);
    float2 v = t[idx];
    return fmaf(fr, v.y, v.x);
}

// Replicated-table variant: t = rep2 + lane; entries strided by 32 lanes
// -> LDS.64 half-warp phases hit all 32 banks once -> conflict-free.
__device__ __forceinline__ float plin_eval_rep(const float2* __restrict__ t, float y) {
    int  idx = (int)y;
    float fr = y - floorf(y);
    float2 v = t[idx * 32];
    return fmaf(fr, v.y, v.x);
}

__global__ __launch_bounds__(NT, 1)
void counter_kernel(const float* __restrict__ boxes,   // (n,4,64)
                    const float* __restrict__ attn,    // (n,64)
                    const float* __restrict__ fw,      // (16,17)
                    float* __restrict__ out)           // (n,11)
{
    __shared__ float2 tab[8][NPW + 1];          // (csum, w_next) per fn
    __shared__ float2 rep2[(NPW + 1) * 32];     // f2 table replicated per lane
    __shared__ float  ds[M * M];                // dedup scores, PRE-SCALED by 16
    __shared__ float  sim[M * M];               // full sim matrix
    __shared__ unsigned short pairs[NT * PPT];  // packed (j | k<<8)
    __shared__ float  att_s[M], area_s[M];
    __shared__ float  bx1[M], by1[M], bx2[M], by2[M];
    __shared__ float  part[12 * M];
    __shared__ float  rowinv[M];
    __shared__ float  wredA[NW], wredB[NW];

    const int tid = threadIdx.x;
    const int bi  = blockIdx.x;

    // ---- Phase 0: build plin tables (fns 0..7) ----
    if (tid < 8) {
        const int fn = tid;
        float w[NPW + 1];
        float s = 0.0f;
        #pragma unroll
        for (int i = 0; i <= NPW; i++) { w[i] = fabsf(fw[fn * (NPW + 1) + i]); s += w[i]; }
        #pragma unroll
        for (int i = 0; i <= NPW; i++) w[i] = w[i] / s;
        float c = 0.0f;
        #pragma unroll
        for (int i = 0; i <= NPW; i++) {
            c += w[i];
            float wn = w[(i + 1 <= NPW) ? (i + 1) : NPW];
            tab[fn][i] = make_float2(c, wn);
        }
    }
    __syncthreads();

    // ---- Phase 1: replicate f2 table, pair table, inputs ----
    for (int e = tid; e < (NPW + 1) * 32; e += NT)
        rep2[e] = tab[2][e >> 5];

    // pairs diagonal-major: d=1..63, j=0..63-d, k=j+d.
    // Consecutive p -> consecutive j,k -> conflict-free lane access.
    for (int p = tid; p < NT * PPT; p += NT) {
        int j = 0, k = 0;
        if (p < NPAIRS) {
            int cum = 0;
            for (int d = 1; d < 64; d++) {
                int len = 64 - d;
                if (p < cum + len) { j = p - cum; k = j + d; break; }
                cum += len;
            }
        }
        pairs[p] = (unsigned short)(j | (k << 8));
    }

    if (tid < M) {
        const int j = tid;
        att_s[j] = attn[bi * M + j];
        float x1 = boxes[(bi * 4 + 0) * M + j];
        float y1 = boxes[(bi * 4 + 1) * M + j];
        float x2 = boxes[(bi * 4 + 2) * M + j];
        float y2 = boxes[(bi * 4 + 3) * M + j];
        bx1[j] = x1; by1[j] = y1; bx2[j] = x2; by2[j] = y2;
        area_s[j] = fmaxf(x2 - x1, 0.0f) * fmaxf(y2 - y1, 0.0f);
    }
    __syncthreads();

    // ---- Phase 2: ds16 = 16*f3(rel)*f4(dist), dconf, attconf, sim diagonal ----
    const int c = tid & 63;        // column (lane-consecutive)
    const int g = tid >> 6;        // 0..11 row group
    const float attc = att_s[c];
    const float x1c = bx1[c], y1c = by1[c], x2c = bx2[c], y2c = by2[c], arc = area_s[c];

    float attconf = 0.0f;
    if (tid < M)
        attconf = fabsf(plin_eval(tab[5], att_s[tid]) - 0.5f);

    float dconf_local = 0.0f;
    for (int r = g; r < M; r += 12) {
        float rel  = att_s[r] * attc;
        float ix = fminf(bx2[r], x2c) - fmaxf(bx1[r], x1c);
        float iy = fminf(by2[r], y2c) - fmaxf(by1[r], y1c);
        ix = fmaxf(ix, 0.0f); iy = fmaxf(iy, 0.0f);
        float inter = ix * iy;
        float dist  = 1.0f - inter / (area_s[r] + arc - inter + 1e-12f);

        ds[r * M + c] = 16.0f * (plin_eval(tab[3], rel) * plin_eval(tab[4], dist));
        dconf_local += fabsf(plin_eval(tab[6], dist) - 0.5f);
    }

    // diagonal of sim: f2(1)^65 = csum2[16]^65 (pow ladder)
    if (tid < M) {
        float cv  = tab[2][NPW].x;
        float c2  = cv * cv;
        float c4  = c2 * c2;
        float c8  = c4 * c4;
        float c16 = c8 * c8;
        float c32 = c16 * c16;
        float c64 = c32 * c32;
        sim[tid * M + tid] = c64 * cv;
    }
    __syncthreads();

    // ---- Phase 3: hot m^3 loop over off-diagonal pairs (symmetry-halved) ----
    int jj[PPT], kk[PPT];
    #pragma unroll
    for (int q = 0; q < PPT; q++) {
        unsigned short pk = pairs[tid + NT * q];
        jj[q] = pk & 255;
        kk[q] = pk >> 8;
    }

    float prod[PPT];
    #pragma unroll
    for (int q = 0; q < PPT; q++) prod[q] = 1.0f;

    const float2* trep = rep2 + (tid & 31);

    #pragma unroll 2
    for (int l = 0; l < M; l++) {
        const float* __restrict__ row = ds + l * M;
        #pragma unroll
        for (int q = 0; q < PPT; q++) {
            float a = row[jj[q]];
            float b = row[kk[q]];
            float y = 16.0f - fabsf(a - b);   // ds pre-scaled: exact 16*diff
            prod[q] *= plin_eval_rep(trep, y);
        }
    }

    #pragma unroll
    for (int q = 0; q < PPT; q++) {
        const int p = tid + NT * q;
        if (p < NPAIRS) {
            const int j = jj[q], k = kk[q];
            float ad = fabsf(att_s[j] - att_s[k]);
            float y  = fmaf(-16.0f, ad, 16.0f);
            float sv = prod[q] * plin_eval_rep(trep, y);
            sim[j * M + k] = sv;
            sim[k * M + j] = sv;
        }
    }
    __syncthreads();

    // ---- Phase 4: row sums (column-wise reads: conflict-free) -> rowinv ----
    {
        float s = 0.0f;
        for (int k = g; k < M; k += 12)
            s += sim[k * M + c];
        part[g * M + c] = s;
    }
    __syncthreads();
    if (tid < M) {
        float rs = 0.0f;
        #pragma unroll
        for (int gg = 0; gg < 12; gg++) rs += part[gg * M + tid];
        rowinv[tid] = 1.0f / rs;
    }
    __syncthreads();

    // ---- Phase 5: recompute A = f0*f1, accumulate score ----
    float accA = 0.0f;
    for (int r = g; r < M; r += 12) {
        float rel  = att_s[r] * attc;
        float ix = fminf(bx2[r], x2c) - fmaxf(bx1[r], x1c);
        float iy = fminf(by2[r], y2c) - fmaxf(by1[r], y1c);
        ix = fmaxf(ix, 0.0f); iy = fmaxf(iy, 0.0f);
        float inter = ix * iy;
        float dist  = 1.0f - inter / (area_s[r] + arc - inter + 1e-12f);
        float Av = plin_eval(tab[0], rel) * plin_eval(tab[1], dist);
        accA += Av * rowinv[r];
    }
    accA *= rowinv[c];

    float corr = 0.0f;
    if (tid < M) {
        float a = att_s[tid];
        corr = plin_eval(tab[0], a * a) * rowinv[tid];
    }

    float ra  = accA + corr;
    float rbv = dconf_local * (1.0f / 4096.0f) + attconf * (1.0f / 64.0f);

    #pragma unroll
    for (int off = 16; off > 0; off >>= 1) {
        ra  += __shfl_down_sync(0xffffffffu, ra,  off);
        rbv += __shfl_down_sync(0xffffffffu, rbv, off);
    }
    if ((tid & 31) == 0) {
        wredA[tid >> 5] = ra;
        wredB[tid >> 5] = rbv;
    }
    __syncthreads();

    // ---- Phase 6: score -> one-hot * conf ----
    if (tid == 0) {
        float S = 0.0f, B = 0.0f;
        #pragma unroll
        for (int i = 0; i < NW; i++) { S += wredA[i]; B += wredB[i]; }

        float score = sqrtf(S + 1e-20f);
        float conf  = plin_eval(tab[7], B);

        float sc  = fminf(fmaxf(score, 0.0f), (float)OBJ);
        int   i0  = (int)sc;
        float fr  = sc - floorf(sc);
        int   i1  = (i0 + 1 <= OBJ) ? (i0 + 1) : OBJ;

        #pragma unroll
        for (int o = 0; o <= OBJ; o++) {
            float v = 0.0f;
            if (o == i0) v += (1.0f - fr);
            if (o == i1) v += fr;
            out[bi * (OBJ + 1) + o] = conf * v;
        }
    }
}

extern "C" void kernel_launch(void* const* d_in, const int* in_sizes, int n_in,
                              void* d_out, int out_size) {
    const float* boxes = (const float*)d_in[0];   // (n,4,64)
    const float* attn  = (const float*)d_in[1];   // (n,64)
    const float* fwts  = (const float*)d_in[2];   // (16,17)
    float* out = (float*)d_out;                   // (n,11)

    const int n = in_sizes[1] / M;                // 128
    counter_kernel<<<n, NT>>>(boxes, attn, fwts, out);
}